// round 7
// baseline (speedup 1.0000x reference)
#include <cuda_runtime.h>

// Problem constants
#define BI 4
#define HH 16
#define SS 1024
#define DK 64
#define DM 1024
#define RP 2048     // padded relative-position vocab stride (actual range used: 0..2000; embK/embV have 2048 rows)
#define BH (BI*HH)  // 64

// ---------------------------------------------------------------------------
// Scratch (device globals: allocation-free)
// ---------------------------------------------------------------------------
__device__ float g_q[BI*HH*SS*DK];                 // [B,H,S,Dk] 16 MB
__device__ float g_k[BI*HH*SS*DK];
__device__ float g_v[BI*HH*SS*DK];
__device__ float g_P[(size_t)BI*HH*SS*RP];         // P[bh,q,r] = q . embK[r]   536 MB
__device__ float g_logits[(size_t)BI*HH*SS*SS];    // logits / weights (in place) 268 MB
__device__ float g_x[BI*SS*DM];                    // attention out pre-projection, [B,S,H*Dk]

// ---------------------------------------------------------------------------
// Projection GEMM: C[m,n] = sum_k X[m,k]*W[n,k] + bias[n]
// M=4096, N=1024, K=1024. 128x128 tile, BK=16, 256 threads, 8x8/thread.
// mode 0: input g_x, output outp (plain [4096,1024])
// mode 1/2/3: input X, output g_q/g_k/g_v with [B,S,H,Dk] -> [B,H,S,Dk] transpose
// ---------------------------------------------------------------------------
__global__ __launch_bounds__(256, 2)
void gemm_proj(const float* __restrict__ X, const float* __restrict__ W,
               const float* __restrict__ bias, float* outp, int mode)
{
    __shared__ float As[16][128];
    __shared__ float Bs[16][128];

    const int m0 = blockIdx.y * 128;
    const int n0 = blockIdx.x * 128;
    const int tid = threadIdx.x;
    const int tx = tid & 15;       // n-group
    const int ty = tid >> 4;       // m-group
    const int lr = tid >> 1;       // loader row 0..127
    const int lc = (tid & 1) * 8;  // loader col base (0 or 8)

    const float* Xp = (mode == 0) ? (const float*)g_x : X;

    float acc[8][8];
#pragma unroll
    for (int i = 0; i < 8; i++)
#pragma unroll
        for (int j = 0; j < 8; j++) acc[i][j] = 0.f;

    const float* Ap = Xp + (m0 + lr) * DM + lc;
    const float* Bp = W  + (n0 + lr) * DM + lc;

    for (int k0 = 0; k0 < DM; k0 += 16) {
        float4 a0 = *(const float4*)(Ap + k0);
        float4 a1 = *(const float4*)(Ap + k0 + 4);
        float4 b0 = *(const float4*)(Bp + k0);
        float4 b1 = *(const float4*)(Bp + k0 + 4);
        __syncthreads();
        As[lc+0][lr] = a0.x; As[lc+1][lr] = a0.y; As[lc+2][lr] = a0.z; As[lc+3][lr] = a0.w;
        As[lc+4][lr] = a1.x; As[lc+5][lr] = a1.y; As[lc+6][lr] = a1.z; As[lc+7][lr] = a1.w;
        Bs[lc+0][lr] = b0.x; Bs[lc+1][lr] = b0.y; Bs[lc+2][lr] = b0.z; Bs[lc+3][lr] = b0.w;
        Bs[lc+4][lr] = b1.x; Bs[lc+5][lr] = b1.y; Bs[lc+6][lr] = b1.z; Bs[lc+7][lr] = b1.w;
        __syncthreads();
#pragma unroll
        for (int kk = 0; kk < 16; kk++) {
            float a[8], b[8];
            *(float4*)&a[0] = *(const float4*)&As[kk][ty*8];
            *(float4*)&a[4] = *(const float4*)&As[kk][ty*8+4];
            *(float4*)&b[0] = *(const float4*)&Bs[kk][tx*8];
            *(float4*)&b[4] = *(const float4*)&Bs[kk][tx*8+4];
#pragma unroll
            for (int i = 0; i < 8; i++)
#pragma unroll
                for (int j = 0; j < 8; j++)
                    acc[i][j] = fmaf(a[i], b[j], acc[i][j]);
        }
    }

    float bvl[8];
#pragma unroll
    for (int j = 0; j < 8; j++) bvl[j] = bias[n0 + tx*8 + j];

    if (mode == 0) {
#pragma unroll
        for (int i = 0; i < 8; i++) {
            int m = m0 + ty*8 + i;
#pragma unroll
            for (int j = 0; j < 8; j++)
                outp[m * DM + n0 + tx*8 + j] = acc[i][j] + bvl[j];
        }
    } else {
        float* dst = (mode == 1) ? g_q : (mode == 2 ? g_k : g_v);
#pragma unroll
        for (int i = 0; i < 8; i++) {
            int m = m0 + ty*8 + i;
            int b = m >> 10, s = m & 1023;
#pragma unroll
            for (int j = 0; j < 8; j++) {
                int n = n0 + tx*8 + j;
                int h = n >> 6, d = n & 63;
                dst[((b*HH + h)*SS + s)*DK + d] = acc[i][j] + bvl[j];
            }
        }
    }
}

// ---------------------------------------------------------------------------
// P GEMM: P[row, r] = sum_d Qflat[row, d] * embK[r, d]
// M = 65536 (bh*S+q), N = 2048 (full padded vocab, valid rows), K = 64
// 128x128 tile, BK=32 (2 chunks), 256 threads, 8x8/thread
// ---------------------------------------------------------------------------
__global__ __launch_bounds__(256, 2)
void gemm_P_kernel(const float* __restrict__ embK)
{
    __shared__ float As[32][128];
    __shared__ float Bs[32][128];

    const int m0 = blockIdx.y * 128;
    const int n0 = blockIdx.x * 128;
    const int tid = threadIdx.x;
    const int tx = tid & 15;
    const int ty = tid >> 4;
    const int lr = tid >> 1;         // 0..127
    const int lc = (tid & 1) * 16;   // 0 or 16

    float acc[8][8];
#pragma unroll
    for (int i = 0; i < 8; i++)
#pragma unroll
        for (int j = 0; j < 8; j++) acc[i][j] = 0.f;

    for (int k0 = 0; k0 < DK; k0 += 32) {
        const float* Ap = g_q + (m0 + lr) * DK + k0 + lc;
        const float* Bp = embK + (n0 + lr) * DK + k0 + lc;
        float4 av[4], bv4[4];
#pragma unroll
        for (int i = 0; i < 4; i++) {
            av[i]  = *(const float4*)(Ap + i*4);
            bv4[i] = *(const float4*)(Bp + i*4);
        }
        __syncthreads();
#pragma unroll
        for (int i = 0; i < 4; i++) {
            As[lc+i*4+0][lr] = av[i].x; As[lc+i*4+1][lr] = av[i].y;
            As[lc+i*4+2][lr] = av[i].z; As[lc+i*4+3][lr] = av[i].w;
            Bs[lc+i*4+0][lr] = bv4[i].x; Bs[lc+i*4+1][lr] = bv4[i].y;
            Bs[lc+i*4+2][lr] = bv4[i].z; Bs[lc+i*4+3][lr] = bv4[i].w;
        }
        __syncthreads();
#pragma unroll 16
        for (int kk = 0; kk < 32; kk++) {
            float a[8], b[8];
            *(float4*)&a[0] = *(const float4*)&As[kk][ty*8];
            *(float4*)&a[4] = *(const float4*)&As[kk][ty*8+4];
            *(float4*)&b[0] = *(const float4*)&Bs[kk][tx*8];
            *(float4*)&b[4] = *(const float4*)&Bs[kk][tx*8+4];
#pragma unroll
            for (int i = 0; i < 8; i++)
#pragma unroll
                for (int j = 0; j < 8; j++)
                    acc[i][j] = fmaf(a[i], b[j], acc[i][j]);
        }
    }

#pragma unroll
    for (int i = 0; i < 8; i++) {
        int row = m0 + ty*8 + i;
#pragma unroll
        for (int j = 0; j < 8; j++)
            g_P[(size_t)row * RP + n0 + tx*8 + j] = acc[i][j];
    }
}

// ---------------------------------------------------------------------------
// Logits: logits[bh,q,k] = sum_d q[bh,q,d]*k[bh,k,d] + P[bh,q, clamp(k-q+1000,0,2000)]
// Per-bh batched GEMM, 128x128 tile, K=64 (BK=32), 256 threads
// ---------------------------------------------------------------------------
__global__ __launch_bounds__(256, 2)
void logits_kernel()
{
    __shared__ float As[32][128];
    __shared__ float Bs[32][128];

    const int bh = blockIdx.z;
    const int q0 = blockIdx.y * 128;
    const int k0g = blockIdx.x * 128;
    const int tid = threadIdx.x;
    const int tx = tid & 15;
    const int ty = tid >> 4;
    const int lr = tid >> 1;
    const int lc = (tid & 1) * 16;

    const float* Qb = g_q + bh * SS * DK;
    const float* Kb = g_k + bh * SS * DK;

    float acc[8][8];
#pragma unroll
    for (int i = 0; i < 8; i++)
#pragma unroll
        for (int j = 0; j < 8; j++) acc[i][j] = 0.f;

    for (int c0 = 0; c0 < DK; c0 += 32) {
        const float* Ap = Qb + (q0 + lr) * DK + c0 + lc;
        const float* Bp = Kb + (k0g + lr) * DK + c0 + lc;
        float4 av[4], bv4[4];
#pragma unroll
        for (int i = 0; i < 4; i++) {
            av[i]  = *(const float4*)(Ap + i*4);
            bv4[i] = *(const float4*)(Bp + i*4);
        }
        __syncthreads();
#pragma unroll
        for (int i = 0; i < 4; i++) {
            As[lc+i*4+0][lr] = av[i].x; As[lc+i*4+1][lr] = av[i].y;
            As[lc+i*4+2][lr] = av[i].z; As[lc+i*4+3][lr] = av[i].w;
            Bs[lc+i*4+0][lr] = bv4[i].x; Bs[lc+i*4+1][lr] = bv4[i].y;
            Bs[lc+i*4+2][lr] = bv4[i].z; Bs[lc+i*4+3][lr] = bv4[i].w;
        }
        __syncthreads();
#pragma unroll 16
        for (int kk = 0; kk < 32; kk++) {
            float a[8], b[8];
            *(float4*)&a[0] = *(const float4*)&As[kk][ty*8];
            *(float4*)&a[4] = *(const float4*)&As[kk][ty*8+4];
            *(float4*)&b[0] = *(const float4*)&Bs[kk][tx*8];
            *(float4*)&b[4] = *(const float4*)&Bs[kk][tx*8+4];
#pragma unroll
            for (int i = 0; i < 8; i++)
#pragma unroll
                for (int j = 0; j < 8; j++)
                    acc[i][j] = fmaf(a[i], b[j], acc[i][j]);
        }
    }

#pragma unroll
    for (int i = 0; i < 8; i++) {
        int q = q0 + ty*8 + i;
        const float* Prow = g_P + (size_t)(bh * SS + q) * RP;
        float* lrow = g_logits + (size_t)bh * SS * SS + (size_t)q * SS;
#pragma unroll
        for (int j = 0; j < 8; j++) {
            int k = k0g + tx*8 + j;
            int rel = k - q + 1000;
            rel = rel < 0 ? 0 : (rel > 2000 ? 2000 : rel);
            lrow[k] = acc[i][j] + Prow[rel];
        }
    }
}

// ---------------------------------------------------------------------------
// Row softmax over g_logits (in place), optional copy to weights output
// ---------------------------------------------------------------------------
__global__ __launch_bounds__(256)
void softmax_kernel(float* __restrict__ wout)
{
    __shared__ float red[8];
    const int row = blockIdx.x;
    float* rp = g_logits + (size_t)row * SS;
    const int tid = threadIdx.x;

    float4 v = *(const float4*)&rp[tid * 4];
    float m = fmaxf(fmaxf(v.x, v.y), fmaxf(v.z, v.w));
#pragma unroll
    for (int o = 16; o; o >>= 1) m = fmaxf(m, __shfl_xor_sync(0xffffffffu, m, o));
    if ((tid & 31) == 0) red[tid >> 5] = m;
    __syncthreads();
    float bm = fmaxf(fmaxf(fmaxf(red[0], red[1]), fmaxf(red[2], red[3])),
                     fmaxf(fmaxf(red[4], red[5]), fmaxf(red[6], red[7])));

    float e0 = __expf(v.x - bm), e1 = __expf(v.y - bm);
    float e2 = __expf(v.z - bm), e3 = __expf(v.w - bm);
    float s = (e0 + e1) + (e2 + e3);
#pragma unroll
    for (int o = 16; o; o >>= 1) s += __shfl_xor_sync(0xffffffffu, s, o);
    __syncthreads();
    if ((tid & 31) == 0) red[tid >> 5] = s;
    __syncthreads();
    float bs = ((red[0] + red[1]) + (red[2] + red[3])) + ((red[4] + red[5]) + (red[6] + red[7]));
    float inv = 1.0f / bs;

    float4 o4 = make_float4(e0 * inv, e1 * inv, e2 * inv, e3 * inv);
    *(float4*)&rp[tid * 4] = o4;
    if (wout) *(float4*)&wout[(size_t)row * SS + tid * 4] = o4;
}

// ---------------------------------------------------------------------------
// AV kernel: x[bh,q,d] = sum_k w[q,k]*v[k,d] + sum_j wsh[q,j]*embV[j,d]
// where wsh[q,j] aggregates w over the clipped relative index j = clamp(k-q+1000).
// Block: 128 threads, tile 128q x 64d, 8x8 per thread. Phase1 over k (32-tiles),
// Phase2 over relative-window j (32-tiles). Output -> g_x in [B,S,H*Dk].
// ---------------------------------------------------------------------------
__global__ __launch_bounds__(128, 4)
void attn_av(const float* __restrict__ embV)
{
    __shared__ float WsT[32][128];  // [k-or-j local][q local]
    __shared__ float Vs[32][68];    // [k-or-j local][d], padded stride

    const int bh = blockIdx.y;
    const int q0 = blockIdx.x * 128;
    const int tid = threadIdx.x;
    const int tx = tid & 7;         // d-group
    const int ty = tid >> 3;        // q-group (0..15)

    const float* wbase = g_logits + (size_t)bh * SS * SS;
    const float* vbase = g_v + bh * SS * DK;
    const int q = q0 + tid;                  // this thread's loader row
    const float* wr = wbase + (size_t)q * SS;

    float acc[8][8];
#pragma unroll
    for (int i = 0; i < 8; i++)
#pragma unroll
        for (int j = 0; j < 8; j++) acc[i][j] = 0.f;

    // ---- Phase 1: standard W @ V ----
    for (int k0 = 0; k0 < SS; k0 += 32) {
        __syncthreads();
#pragma unroll
        for (int i = 0; i < 8; i++) {
            float4 w4 = *(const float4*)&wr[k0 + i*4];
            WsT[i*4+0][tid] = w4.x; WsT[i*4+1][tid] = w4.y;
            WsT[i*4+2][tid] = w4.z; WsT[i*4+3][tid] = w4.w;
        }
        {
            int vrow = tid >> 2, cb = (tid & 3) * 16;
            const float* vp = vbase + (k0 + vrow) * DK + cb;
#pragma unroll
            for (int i = 0; i < 4; i++)
                *(float4*)&Vs[vrow][cb + i*4] = *(const float4*)&vp[i*4];
        }
        __syncthreads();
#pragma unroll 16
        for (int kk = 0; kk < 32; kk++) {
            float a[8], b[8];
            *(float4*)&a[0] = *(const float4*)&WsT[kk][ty*8];
            *(float4*)&a[4] = *(const float4*)&WsT[kk][ty*8+4];
            *(float4*)&b[0] = *(const float4*)&Vs[kk][tx*8];
            *(float4*)&b[4] = *(const float4*)&Vs[kk][tx*8+4];
#pragma unroll
            for (int i = 0; i < 8; i++)
#pragma unroll
                for (int j = 0; j < 8; j++)
                    acc[i][j] = fmaf(a[i], b[j], acc[i][j]);
        }
    }

    // ---- Phase 2: skewed W @ embV window ----
    const int jlo = max(0, 873 - q0);           // 1000 - (q0+127)
    const int jhi = min(2000, 2023 - q0);       // 1000 + (1023 - q0)
    for (int j0 = jlo; j0 <= jhi; j0 += 32) {
        __syncthreads();
        // Build skewed weights: wsh[q, j] (edge buckets at j=0 / j=2000 absorb clip)
        for (int jj = 0; jj < 32; jj++) {
            int j = j0 + jj;
            float val = 0.f;
            if (j > 0 && j < 2000) {
                int k = j + q - 1000;
                if ((unsigned)k < 1024u) val = wr[k];
            } else if (j == 0) {
                int kmax = q - 1000;             // only q >= 1000
                for (int k = 0; k <= kmax; k++) val += wr[k];
            } else if (j == 2000) {
                for (int k = q + 1000; k < 1024; k++) val += wr[k];  // only q <= 23
            }
            WsT[jj][tid] = val;
        }
        {
            int vrow = tid >> 2, cb = (tid & 3) * 16;
            int j = j0 + vrow;
            if (j < 2048) {
                const float* ep = embV + j * DK + cb;
#pragma unroll
                for (int i = 0; i < 4; i++)
                    *(float4*)&Vs[vrow][cb + i*4] = *(const float4*)&ep[i*4];
            } else {
#pragma unroll
                for (int i = 0; i < 4; i++)
                    *(float4*)&Vs[vrow][cb + i*4] = make_float4(0.f, 0.f, 0.f, 0.f);
            }
        }
        __syncthreads();
#pragma unroll 16
        for (int kk = 0; kk < 32; kk++) {
            float a[8], b[8];
            *(float4*)&a[0] = *(const float4*)&WsT[kk][ty*8];
            *(float4*)&a[4] = *(const float4*)&WsT[kk][ty*8+4];
            *(float4*)&b[0] = *(const float4*)&Vs[kk][tx*8];
            *(float4*)&b[4] = *(const float4*)&Vs[kk][tx*8+4];
#pragma unroll
            for (int i = 0; i < 8; i++)
#pragma unroll
                for (int j = 0; j < 8; j++)
                    acc[i][j] = fmaf(a[i], b[j], acc[i][j]);
        }
    }

    // epilogue: g_x[b, s=q, h*64+d]
    const int b = bh >> 4, h = bh & 15;
#pragma unroll
    for (int i = 0; i < 8; i++) {
        int qq = q0 + ty*8 + i;
#pragma unroll
        for (int j = 0; j < 8; j++)
            g_x[(b*SS + qq)*DM + h*DK + tx*8 + j] = acc[i][j];
    }
}

// ---------------------------------------------------------------------------
// Launch
// ---------------------------------------------------------------------------
extern "C" void kernel_launch(void* const* d_in, const int* in_sizes, int n_in,
                              void* d_out, int out_size)
{
    const float* query = (const float*)d_in[0];
    const float* key_  = (const float*)d_in[1];
    const float* value = (const float*)d_in[2];
    const float* Wq = (const float*)d_in[3];
    const float* bq = (const float*)d_in[4];
    const float* Wk = (const float*)d_in[5];
    const float* bk = (const float*)d_in[6];
    const float* Wv = (const float*)d_in[7];
    const float* bv = (const float*)d_in[8];
    const float* Wo = (const float*)d_in[9];
    const float* bo = (const float*)d_in[10];
    const float* embK = (const float*)d_in[11];
    const float* embV = (const float*)d_in[12];

    float* outp = (float*)d_out;
    const long OUT_N = (long)BI * SS * DM;        // 4,194,304  (out)
    const long W_N   = (long)BI * HH * SS * SS;   // 67,108,864 (weights)

    float* out_main = nullptr;
    float* out_w = nullptr;
    if ((long)out_size >= OUT_N + W_N) { out_main = outp; out_w = outp + OUT_N; }
    else if ((long)out_size >= W_N)    { out_w = outp; }
    else                               { out_main = outp; }

    dim3 gp(DM / 128, (BI * SS) / 128);                       // (8, 32)
    gemm_proj<<<gp, 256>>>(query, Wq, bq, nullptr, 1);
    gemm_proj<<<gp, 256>>>(key_,  Wk, bk, nullptr, 2);
    gemm_proj<<<gp, 256>>>(value, Wv, bv, nullptr, 3);

    gemm_P_kernel<<<dim3(RP / 128, (BI * HH * SS) / 128), 256>>>(embK);  // (16, 512)

    logits_kernel<<<dim3(SS / 128, SS / 128, BI * HH), 256>>>();         // (8, 8, 64)

    softmax_kernel<<<BI * HH * SS, 256>>>(out_w);                        // 65536 rows

    attn_av<<<dim3(SS / 128, BI * HH), 128>>>(embV);                     // (8, 64)

    if (out_main)
        gemm_proj<<<gp, 256>>>(nullptr, Wo, bo, out_main, 0);
}

// round 8
// speedup vs baseline: 1.0006x; 1.0006x over previous
#include <cuda_runtime.h>

// Problem constants
#define BI 4
#define HH 16
#define SS 1024
#define DK 64
#define DM 1024
#define RP 2048     // padded relative-position vocab stride (actual range used: 0..2000; embK/embV have 2048 rows)
#define BH (BI*HH)  // 64

// ---------------------------------------------------------------------------
// Scratch (device globals: allocation-free)
// ---------------------------------------------------------------------------
__device__ float g_q[BI*HH*SS*DK];                 // [B,H,S,Dk] 16 MB
__device__ float g_k[BI*HH*SS*DK];
__device__ float g_v[BI*HH*SS*DK];
__device__ float g_P[(size_t)BI*HH*SS*RP];         // P[bh,q,r] = q . embK[r]   536 MB
__device__ float g_logits[(size_t)BI*HH*SS*SS];    // logits / weights (in place) 268 MB
__device__ float g_x[BI*SS*DM];                    // attention out pre-projection, [B,S,H*Dk]

// ---------------------------------------------------------------------------
// Projection GEMM: C[m,n] = sum_k X[m,k]*W[n,k] + bias[n]
// M=4096, N=1024, K=1024. 128x128 tile, BK=16, 256 threads, 8x8/thread.
// mode 0: input g_x, output outp (plain [4096,1024])
// mode 1/2/3: input X, output g_q/g_k/g_v with [B,S,H,Dk] -> [B,H,S,Dk] transpose
// ---------------------------------------------------------------------------
__global__ __launch_bounds__(256, 2)
void gemm_proj(const float* __restrict__ X, const float* __restrict__ W,
               const float* __restrict__ bias, float* outp, int mode)
{
    __shared__ float As[16][128];
    __shared__ float Bs[16][128];

    const int m0 = blockIdx.y * 128;
    const int n0 = blockIdx.x * 128;
    const int tid = threadIdx.x;
    const int tx = tid & 15;       // n-group
    const int ty = tid >> 4;       // m-group
    const int lr = tid >> 1;       // loader row 0..127
    const int lc = (tid & 1) * 8;  // loader col base (0 or 8)

    const float* Xp = (mode == 0) ? (const float*)g_x : X;

    float acc[8][8];
#pragma unroll
    for (int i = 0; i < 8; i++)
#pragma unroll
        for (int j = 0; j < 8; j++) acc[i][j] = 0.f;

    const float* Ap = Xp + (m0 + lr) * DM + lc;
    const float* Bp = W  + (n0 + lr) * DM + lc;

    for (int k0 = 0; k0 < DM; k0 += 16) {
        float4 a0 = *(const float4*)(Ap + k0);
        float4 a1 = *(const float4*)(Ap + k0 + 4);
        float4 b0 = *(const float4*)(Bp + k0);
        float4 b1 = *(const float4*)(Bp + k0 + 4);
        __syncthreads();
        As[lc+0][lr] = a0.x; As[lc+1][lr] = a0.y; As[lc+2][lr] = a0.z; As[lc+3][lr] = a0.w;
        As[lc+4][lr] = a1.x; As[lc+5][lr] = a1.y; As[lc+6][lr] = a1.z; As[lc+7][lr] = a1.w;
        Bs[lc+0][lr] = b0.x; Bs[lc+1][lr] = b0.y; Bs[lc+2][lr] = b0.z; Bs[lc+3][lr] = b0.w;
        Bs[lc+4][lr] = b1.x; Bs[lc+5][lr] = b1.y; Bs[lc+6][lr] = b1.z; Bs[lc+7][lr] = b1.w;
        __syncthreads();
#pragma unroll
        for (int kk = 0; kk < 16; kk++) {
            float a[8], b[8];
            *(float4*)&a[0] = *(const float4*)&As[kk][ty*8];
            *(float4*)&a[4] = *(const float4*)&As[kk][ty*8+4];
            *(float4*)&b[0] = *(const float4*)&Bs[kk][tx*8];
            *(float4*)&b[4] = *(const float4*)&Bs[kk][tx*8+4];
#pragma unroll
            for (int i = 0; i < 8; i++)
#pragma unroll
                for (int j = 0; j < 8; j++)
                    acc[i][j] = fmaf(a[i], b[j], acc[i][j]);
        }
    }

    float bvl[8];
#pragma unroll
    for (int j = 0; j < 8; j++) bvl[j] = bias[n0 + tx*8 + j];

    if (mode == 0) {
#pragma unroll
        for (int i = 0; i < 8; i++) {
            int m = m0 + ty*8 + i;
#pragma unroll
            for (int j = 0; j < 8; j++)
                outp[m * DM + n0 + tx*8 + j] = acc[i][j] + bvl[j];
        }
    } else {
        float* dst = (mode == 1) ? g_q : (mode == 2 ? g_k : g_v);
#pragma unroll
        for (int i = 0; i < 8; i++) {
            int m = m0 + ty*8 + i;
            int b = m >> 10, s = m & 1023;
#pragma unroll
            for (int j = 0; j < 8; j++) {
                int n = n0 + tx*8 + j;
                int h = n >> 6, d = n & 63;
                dst[((b*HH + h)*SS + s)*DK + d] = acc[i][j] + bvl[j];
            }
        }
    }
}

// ---------------------------------------------------------------------------
// P GEMM: P[row, r] = sum_d Qflat[row, d] * embK[r, d]
// M = 65536 (bh*S+q), N = 2048 (full padded vocab, valid rows), K = 64
// 128x128 tile, BK=32 (2 chunks), 256 threads, 8x8/thread
// ---------------------------------------------------------------------------
__global__ __launch_bounds__(256, 2)
void gemm_P_kernel(const float* __restrict__ embK)
{
    __shared__ float As[32][128];
    __shared__ float Bs[32][128];

    const int m0 = blockIdx.y * 128;
    const int n0 = blockIdx.x * 128;
    const int tid = threadIdx.x;
    const int tx = tid & 15;
    const int ty = tid >> 4;
    const int lr = tid >> 1;         // 0..127
    const int lc = (tid & 1) * 16;   // 0 or 16

    float acc[8][8];
#pragma unroll
    for (int i = 0; i < 8; i++)
#pragma unroll
        for (int j = 0; j < 8; j++) acc[i][j] = 0.f;

    for (int k0 = 0; k0 < DK; k0 += 32) {
        const float* Ap = g_q + (m0 + lr) * DK + k0 + lc;
        const float* Bp = embK + (n0 + lr) * DK + k0 + lc;
        float4 av[4], bv4[4];
#pragma unroll
        for (int i = 0; i < 4; i++) {
            av[i]  = *(const float4*)(Ap + i*4);
            bv4[i] = *(const float4*)(Bp + i*4);
        }
        __syncthreads();
#pragma unroll
        for (int i = 0; i < 4; i++) {
            As[lc+i*4+0][lr] = av[i].x; As[lc+i*4+1][lr] = av[i].y;
            As[lc+i*4+2][lr] = av[i].z; As[lc+i*4+3][lr] = av[i].w;
            Bs[lc+i*4+0][lr] = bv4[i].x; Bs[lc+i*4+1][lr] = bv4[i].y;
            Bs[lc+i*4+2][lr] = bv4[i].z; Bs[lc+i*4+3][lr] = bv4[i].w;
        }
        __syncthreads();
#pragma unroll 16
        for (int kk = 0; kk < 32; kk++) {
            float a[8], b[8];
            *(float4*)&a[0] = *(const float4*)&As[kk][ty*8];
            *(float4*)&a[4] = *(const float4*)&As[kk][ty*8+4];
            *(float4*)&b[0] = *(const float4*)&Bs[kk][tx*8];
            *(float4*)&b[4] = *(const float4*)&Bs[kk][tx*8+4];
#pragma unroll
            for (int i = 0; i < 8; i++)
#pragma unroll
                for (int j = 0; j < 8; j++)
                    acc[i][j] = fmaf(a[i], b[j], acc[i][j]);
        }
    }

#pragma unroll
    for (int i = 0; i < 8; i++) {
        int row = m0 + ty*8 + i;
#pragma unroll
        for (int j = 0; j < 8; j++)
            g_P[(size_t)row * RP + n0 + tx*8 + j] = acc[i][j];
    }
}

// ---------------------------------------------------------------------------
// Logits: logits[bh,q,k] = sum_d q[bh,q,d]*k[bh,k,d] + P[bh,q, clamp(k-q+1000,0,2000)]
// Per-bh batched GEMM, 128x128 tile, K=64 (BK=32), 256 threads
// ---------------------------------------------------------------------------
__global__ __launch_bounds__(256, 2)
void logits_kernel()
{
    __shared__ float As[32][128];
    __shared__ float Bs[32][128];

    const int bh = blockIdx.z;
    const int q0 = blockIdx.y * 128;
    const int k0g = blockIdx.x * 128;
    const int tid = threadIdx.x;
    const int tx = tid & 15;
    const int ty = tid >> 4;
    const int lr = tid >> 1;
    const int lc = (tid & 1) * 16;

    const float* Qb = g_q + bh * SS * DK;
    const float* Kb = g_k + bh * SS * DK;

    float acc[8][8];
#pragma unroll
    for (int i = 0; i < 8; i++)
#pragma unroll
        for (int j = 0; j < 8; j++) acc[i][j] = 0.f;

    for (int c0 = 0; c0 < DK; c0 += 32) {
        const float* Ap = Qb + (q0 + lr) * DK + c0 + lc;
        const float* Bp = Kb + (k0g + lr) * DK + c0 + lc;
        float4 av[4], bv4[4];
#pragma unroll
        for (int i = 0; i < 4; i++) {
            av[i]  = *(const float4*)(Ap + i*4);
            bv4[i] = *(const float4*)(Bp + i*4);
        }
        __syncthreads();
#pragma unroll
        for (int i = 0; i < 4; i++) {
            As[lc+i*4+0][lr] = av[i].x; As[lc+i*4+1][lr] = av[i].y;
            As[lc+i*4+2][lr] = av[i].z; As[lc+i*4+3][lr] = av[i].w;
            Bs[lc+i*4+0][lr] = bv4[i].x; Bs[lc+i*4+1][lr] = bv4[i].y;
            Bs[lc+i*4+2][lr] = bv4[i].z; Bs[lc+i*4+3][lr] = bv4[i].w;
        }
        __syncthreads();
#pragma unroll 16
        for (int kk = 0; kk < 32; kk++) {
            float a[8], b[8];
            *(float4*)&a[0] = *(const float4*)&As[kk][ty*8];
            *(float4*)&a[4] = *(const float4*)&As[kk][ty*8+4];
            *(float4*)&b[0] = *(const float4*)&Bs[kk][tx*8];
            *(float4*)&b[4] = *(const float4*)&Bs[kk][tx*8+4];
#pragma unroll
            for (int i = 0; i < 8; i++)
#pragma unroll
                for (int j = 0; j < 8; j++)
                    acc[i][j] = fmaf(a[i], b[j], acc[i][j]);
        }
    }

#pragma unroll
    for (int i = 0; i < 8; i++) {
        int q = q0 + ty*8 + i;
        const float* Prow = g_P + (size_t)(bh * SS + q) * RP;
        float* lrow = g_logits + (size_t)bh * SS * SS + (size_t)q * SS;
#pragma unroll
        for (int j = 0; j < 8; j++) {
            int k = k0g + tx*8 + j;
            int rel = k - q + 1000;
            rel = rel < 0 ? 0 : (rel > 2000 ? 2000 : rel);
            lrow[k] = acc[i][j] + Prow[rel];
        }
    }
}

// ---------------------------------------------------------------------------
// Row softmax over g_logits (in place), optional copy to weights output
// ---------------------------------------------------------------------------
__global__ __launch_bounds__(256)
void softmax_kernel(float* __restrict__ wout)
{
    __shared__ float red[8];
    const int row = blockIdx.x;
    float* rp = g_logits + (size_t)row * SS;
    const int tid = threadIdx.x;

    float4 v = *(const float4*)&rp[tid * 4];
    float m = fmaxf(fmaxf(v.x, v.y), fmaxf(v.z, v.w));
#pragma unroll
    for (int o = 16; o; o >>= 1) m = fmaxf(m, __shfl_xor_sync(0xffffffffu, m, o));
    if ((tid & 31) == 0) red[tid >> 5] = m;
    __syncthreads();
    float bm = fmaxf(fmaxf(fmaxf(red[0], red[1]), fmaxf(red[2], red[3])),
                     fmaxf(fmaxf(red[4], red[5]), fmaxf(red[6], red[7])));

    float e0 = __expf(v.x - bm), e1 = __expf(v.y - bm);
    float e2 = __expf(v.z - bm), e3 = __expf(v.w - bm);
    float s = (e0 + e1) + (e2 + e3);
#pragma unroll
    for (int o = 16; o; o >>= 1) s += __shfl_xor_sync(0xffffffffu, s, o);
    __syncthreads();
    if ((tid & 31) == 0) red[tid >> 5] = s;
    __syncthreads();
    float bs = ((red[0] + red[1]) + (red[2] + red[3])) + ((red[4] + red[5]) + (red[6] + red[7]));
    float inv = 1.0f / bs;

    float4 o4 = make_float4(e0 * inv, e1 * inv, e2 * inv, e3 * inv);
    *(float4*)&rp[tid * 4] = o4;
    if (wout) *(float4*)&wout[(size_t)row * SS + tid * 4] = o4;
}

// ---------------------------------------------------------------------------
// AV kernel: x[bh,q,d] = sum_k w[q,k]*v[k,d] + sum_j wsh[q,j]*embV[j,d]
// where wsh[q,j] aggregates w over the clipped relative index j = clamp(k-q+1000).
// Block: 128 threads, tile 128q x 64d, 8x8 per thread. Phase1 over k (32-tiles),
// Phase2 over relative-window j (32-tiles). Output -> g_x in [B,S,H*Dk].
// ---------------------------------------------------------------------------
__global__ __launch_bounds__(128, 4)
void attn_av(const float* __restrict__ embV)
{
    __shared__ float WsT[32][128];  // [k-or-j local][q local]
    __shared__ float Vs[32][68];    // [k-or-j local][d], padded stride

    const int bh = blockIdx.y;
    const int q0 = blockIdx.x * 128;
    const int tid = threadIdx.x;
    const int tx = tid & 7;         // d-group
    const int ty = tid >> 3;        // q-group (0..15)

    const float* wbase = g_logits + (size_t)bh * SS * SS;
    const float* vbase = g_v + bh * SS * DK;
    const int q = q0 + tid;                  // this thread's loader row
    const float* wr = wbase + (size_t)q * SS;

    float acc[8][8];
#pragma unroll
    for (int i = 0; i < 8; i++)
#pragma unroll
        for (int j = 0; j < 8; j++) acc[i][j] = 0.f;

    // ---- Phase 1: standard W @ V ----
    for (int k0 = 0; k0 < SS; k0 += 32) {
        __syncthreads();
#pragma unroll
        for (int i = 0; i < 8; i++) {
            float4 w4 = *(const float4*)&wr[k0 + i*4];
            WsT[i*4+0][tid] = w4.x; WsT[i*4+1][tid] = w4.y;
            WsT[i*4+2][tid] = w4.z; WsT[i*4+3][tid] = w4.w;
        }
        {
            int vrow = tid >> 2, cb = (tid & 3) * 16;
            const float* vp = vbase + (k0 + vrow) * DK + cb;
#pragma unroll
            for (int i = 0; i < 4; i++)
                *(float4*)&Vs[vrow][cb + i*4] = *(const float4*)&vp[i*4];
        }
        __syncthreads();
#pragma unroll 16
        for (int kk = 0; kk < 32; kk++) {
            float a[8], b[8];
            *(float4*)&a[0] = *(const float4*)&WsT[kk][ty*8];
            *(float4*)&a[4] = *(const float4*)&WsT[kk][ty*8+4];
            *(float4*)&b[0] = *(const float4*)&Vs[kk][tx*8];
            *(float4*)&b[4] = *(const float4*)&Vs[kk][tx*8+4];
#pragma unroll
            for (int i = 0; i < 8; i++)
#pragma unroll
                for (int j = 0; j < 8; j++)
                    acc[i][j] = fmaf(a[i], b[j], acc[i][j]);
        }
    }

    // ---- Phase 2: skewed W @ embV window ----
    const int jlo = max(0, 873 - q0);           // 1000 - (q0+127)
    const int jhi = min(2000, 2023 - q0);       // 1000 + (1023 - q0)
    for (int j0 = jlo; j0 <= jhi; j0 += 32) {
        __syncthreads();
        // Build skewed weights: wsh[q, j] (edge buckets at j=0 / j=2000 absorb clip)
        for (int jj = 0; jj < 32; jj++) {
            int j = j0 + jj;
            float val = 0.f;
            if (j > 0 && j < 2000) {
                int k = j + q - 1000;
                if ((unsigned)k < 1024u) val = wr[k];
            } else if (j == 0) {
                int kmax = q - 1000;             // only q >= 1000
                for (int k = 0; k <= kmax; k++) val += wr[k];
            } else if (j == 2000) {
                for (int k = q + 1000; k < 1024; k++) val += wr[k];  // only q <= 23
            }
            WsT[jj][tid] = val;
        }
        {
            int vrow = tid >> 2, cb = (tid & 3) * 16;
            int j = j0 + vrow;
            if (j < 2048) {
                const float* ep = embV + j * DK + cb;
#pragma unroll
                for (int i = 0; i < 4; i++)
                    *(float4*)&Vs[vrow][cb + i*4] = *(const float4*)&ep[i*4];
            } else {
#pragma unroll
                for (int i = 0; i < 4; i++)
                    *(float4*)&Vs[vrow][cb + i*4] = make_float4(0.f, 0.f, 0.f, 0.f);
            }
        }
        __syncthreads();
#pragma unroll 16
        for (int kk = 0; kk < 32; kk++) {
            float a[8], b[8];
            *(float4*)&a[0] = *(const float4*)&WsT[kk][ty*8];
            *(float4*)&a[4] = *(const float4*)&WsT[kk][ty*8+4];
            *(float4*)&b[0] = *(const float4*)&Vs[kk][tx*8];
            *(float4*)&b[4] = *(const float4*)&Vs[kk][tx*8+4];
#pragma unroll
            for (int i = 0; i < 8; i++)
#pragma unroll
                for (int j = 0; j < 8; j++)
                    acc[i][j] = fmaf(a[i], b[j], acc[i][j]);
        }
    }

    // epilogue: g_x[b, s=q, h*64+d]
    const int b = bh >> 4, h = bh & 15;
#pragma unroll
    for (int i = 0; i < 8; i++) {
        int qq = q0 + ty*8 + i;
#pragma unroll
        for (int j = 0; j < 8; j++)
            g_x[(b*SS + qq)*DM + h*DK + tx*8 + j] = acc[i][j];
    }
}

// ---------------------------------------------------------------------------
// Launch
// ---------------------------------------------------------------------------
extern "C" void kernel_launch(void* const* d_in, const int* in_sizes, int n_in,
                              void* d_out, int out_size)
{
    const float* query = (const float*)d_in[0];
    const float* key_  = (const float*)d_in[1];
    const float* value = (const float*)d_in[2];
    const float* Wq = (const float*)d_in[3];
    const float* bq = (const float*)d_in[4];
    const float* Wk = (const float*)d_in[5];
    const float* bk = (const float*)d_in[6];
    const float* Wv = (const float*)d_in[7];
    const float* bv = (const float*)d_in[8];
    const float* Wo = (const float*)d_in[9];
    const float* bo = (const float*)d_in[10];
    const float* embK = (const float*)d_in[11];
    const float* embV = (const float*)d_in[12];

    float* outp = (float*)d_out;
    const long OUT_N = (long)BI * SS * DM;        // 4,194,304  (out)
    const long W_N   = (long)BI * HH * SS * SS;   // 67,108,864 (weights)

    float* out_main = nullptr;
    float* out_w = nullptr;
    if ((long)out_size >= OUT_N + W_N) { out_main = outp; out_w = outp + OUT_N; }
    else if ((long)out_size >= W_N)    { out_w = outp; }
    else                               { out_main = outp; }

    dim3 gp(DM / 128, (BI * SS) / 128);                       // (8, 32)
    gemm_proj<<<gp, 256>>>(query, Wq, bq, nullptr, 1);
    gemm_proj<<<gp, 256>>>(key_,  Wk, bk, nullptr, 2);
    gemm_proj<<<gp, 256>>>(value, Wv, bv, nullptr, 3);

    gemm_P_kernel<<<dim3(RP / 128, (BI * HH * SS) / 128), 256>>>(embK);  // (16, 512)

    logits_kernel<<<dim3(SS / 128, SS / 128, BI * HH), 256>>>();         // (8, 8, 64)

    softmax_kernel<<<BI * HH * SS, 256>>>(out_w);                        // 65536 rows

    attn_av<<<dim3(SS / 128, BI * HH), 128>>>(embV);                     // (8, 64)

    if (out_main)
        gemm_proj<<<gp, 256>>>(nullptr, Wo, bo, out_main, 0);
}

// round 9
// speedup vs baseline: 1.1843x; 1.1837x over previous
#include <cuda_runtime.h>

// Problem constants
#define BI 4
#define HH 16
#define SS 1024
#define DK 64
#define DM 1024
#define BH (BI*HH)  // 64

// ---------------------------------------------------------------------------
// Scratch (device globals: allocation-free)
// ---------------------------------------------------------------------------
__device__ float g_q[BI*HH*SS*DK];                 // [B,H,S,Dk] 16 MB
__device__ float g_k[BI*HH*SS*DK];
__device__ float g_v[BI*HH*SS*DK];
__device__ float g_logits[(size_t)BI*HH*SS*SS];    // logits (pre-softmax) 268 MB
__device__ float g_x[BI*SS*DM];                    // attention out pre-projection, [B,S,H*Dk]

// ---------------------------------------------------------------------------
// Projection GEMM: C[m,n] = sum_k X[m,k]*W[n,k] + bias[n]
// M=4096, N=1024, K=1024. 128x128 tile, BK=16, 256 threads, 8x8/thread.
// mode 0: input g_x, output outp (plain [4096,1024])
// mode 1/2/3: input X, output g_q/g_k/g_v with [B,S,H,Dk] -> [B,H,S,Dk] transpose
// ---------------------------------------------------------------------------
__global__ __launch_bounds__(256, 2)
void gemm_proj(const float* __restrict__ X, const float* __restrict__ W,
               const float* __restrict__ bias, float* outp, int mode)
{
    __shared__ float As[16][128];
    __shared__ float Bs[16][128];

    const int m0 = blockIdx.y * 128;
    const int n0 = blockIdx.x * 128;
    const int tid = threadIdx.x;
    const int tx = tid & 15;       // n-group
    const int ty = tid >> 4;       // m-group
    const int lr = tid >> 1;       // loader row 0..127
    const int lc = (tid & 1) * 8;  // loader col base (0 or 8)

    const float* Xp = (mode == 0) ? (const float*)g_x : X;

    float acc[8][8];
#pragma unroll
    for (int i = 0; i < 8; i++)
#pragma unroll
        for (int j = 0; j < 8; j++) acc[i][j] = 0.f;

    const float* Ap = Xp + (m0 + lr) * DM + lc;
    const float* Bp = W  + (n0 + lr) * DM + lc;

    for (int k0 = 0; k0 < DM; k0 += 16) {
        float4 a0 = *(const float4*)(Ap + k0);
        float4 a1 = *(const float4*)(Ap + k0 + 4);
        float4 b0 = *(const float4*)(Bp + k0);
        float4 b1 = *(const float4*)(Bp + k0 + 4);
        __syncthreads();
        As[lc+0][lr] = a0.x; As[lc+1][lr] = a0.y; As[lc+2][lr] = a0.z; As[lc+3][lr] = a0.w;
        As[lc+4][lr] = a1.x; As[lc+5][lr] = a1.y; As[lc+6][lr] = a1.z; As[lc+7][lr] = a1.w;
        Bs[lc+0][lr] = b0.x; Bs[lc+1][lr] = b0.y; Bs[lc+2][lr] = b0.z; Bs[lc+3][lr] = b0.w;
        Bs[lc+4][lr] = b1.x; Bs[lc+5][lr] = b1.y; Bs[lc+6][lr] = b1.z; Bs[lc+7][lr] = b1.w;
        __syncthreads();
#pragma unroll
        for (int kk = 0; kk < 16; kk++) {
            float a[8], b[8];
            *(float4*)&a[0] = *(const float4*)&As[kk][ty*8];
            *(float4*)&a[4] = *(const float4*)&As[kk][ty*8+4];
            *(float4*)&b[0] = *(const float4*)&Bs[kk][tx*8];
            *(float4*)&b[4] = *(const float4*)&Bs[kk][tx*8+4];
#pragma unroll
            for (int i = 0; i < 8; i++)
#pragma unroll
                for (int j = 0; j < 8; j++)
                    acc[i][j] = fmaf(a[i], b[j], acc[i][j]);
        }
    }

    float bvl[8];
#pragma unroll
    for (int j = 0; j < 8; j++) bvl[j] = bias[n0 + tx*8 + j];

    if (mode == 0) {
#pragma unroll
        for (int i = 0; i < 8; i++) {
            int m = m0 + ty*8 + i;
#pragma unroll
            for (int j = 0; j < 8; j++)
                outp[m * DM + n0 + tx*8 + j] = acc[i][j] + bvl[j];
        }
    } else {
        float* dst = (mode == 1) ? g_q : (mode == 2 ? g_k : g_v);
#pragma unroll
        for (int i = 0; i < 8; i++) {
            int m = m0 + ty*8 + i;
            int b = m >> 10, s = m & 1023;
#pragma unroll
            for (int j = 0; j < 8; j++) {
                int n = n0 + tx*8 + j;
                int h = n >> 6, d = n & 63;
                dst[((b*HH + h)*SS + s)*DK + d] = acc[i][j] + bvl[j];
            }
        }
    }
}

// ---------------------------------------------------------------------------
// Fused logits kernel:
//   logits[bh,q,k] = sum_d q[bh,q,d]*k[bh,k,d]
//                  + sum_d q[bh,q,d]*embK[clamp(k-q+1000,0,2000), d]
// Per 128x128 (q,k) tile the bias needs embK rows in a 255-wide diagonal
// window r = k-q+1000 in [rbase, rbase+254], rbase = k0-q0+873.
// Phase A: standard QK^T GEMM (two 32-d chunks).
// Phase B: Toeplitz accumulation against the embK window (two 32-d chunks).
// Dynamic smem: As[32][128] + Bs[32][128] + Es[32][264] = 66,560 B.
// ---------------------------------------------------------------------------
#define ESTR 264
#define LOGITS_SMEM ((32*128 + 32*128 + 32*ESTR) * 4)

__global__ __launch_bounds__(256)
void logits_fused(const float* __restrict__ embK)
{
    extern __shared__ float sm[];
    float* As = sm;                 // [32][128]
    float* Bs = sm + 32*128;        // [32][128]
    float* Es = sm + 64*128;        // [32][ESTR]

    const int bh = blockIdx.z;
    const int q0 = blockIdx.y * 128;
    const int k0g = blockIdx.x * 128;
    const int tid = threadIdx.x;
    const int tx = tid & 15;
    const int ty = tid >> 4;
    const int lr = tid >> 1;
    const int lc = (tid & 1) * 16;

    const float* Qb = g_q + bh * SS * DK;
    const float* Kb = g_k + bh * SS * DK;

    float acc[8][8];
#pragma unroll
    for (int i = 0; i < 8; i++)
#pragma unroll
        for (int j = 0; j < 8; j++) acc[i][j] = 0.f;

    // ---- Phase A: Q @ K^T ----
    for (int c0 = 0; c0 < DK; c0 += 32) {
        const float* Ap = Qb + (q0 + lr) * DK + c0 + lc;
        const float* Bp = Kb + (k0g + lr) * DK + c0 + lc;
        float4 av[4], bv4[4];
#pragma unroll
        for (int i = 0; i < 4; i++) {
            av[i]  = *(const float4*)(Ap + i*4);
            bv4[i] = *(const float4*)(Bp + i*4);
        }
        __syncthreads();
#pragma unroll
        for (int i = 0; i < 4; i++) {
            As[(lc+i*4+0)*128 + lr] = av[i].x; As[(lc+i*4+1)*128 + lr] = av[i].y;
            As[(lc+i*4+2)*128 + lr] = av[i].z; As[(lc+i*4+3)*128 + lr] = av[i].w;
            Bs[(lc+i*4+0)*128 + lr] = bv4[i].x; Bs[(lc+i*4+1)*128 + lr] = bv4[i].y;
            Bs[(lc+i*4+2)*128 + lr] = bv4[i].z; Bs[(lc+i*4+3)*128 + lr] = bv4[i].w;
        }
        __syncthreads();
#pragma unroll 16
        for (int kk = 0; kk < 32; kk++) {
            float a[8], b[8];
            *(float4*)&a[0] = *(const float4*)&As[kk*128 + ty*8];
            *(float4*)&a[4] = *(const float4*)&As[kk*128 + ty*8+4];
            *(float4*)&b[0] = *(const float4*)&Bs[kk*128 + tx*8];
            *(float4*)&b[4] = *(const float4*)&Bs[kk*128 + tx*8+4];
#pragma unroll
            for (int i = 0; i < 8; i++)
#pragma unroll
                for (int j = 0; j < 8; j++)
                    acc[i][j] = fmaf(a[i], b[j], acc[i][j]);
        }
    }

    // ---- Phase B: Toeplitz bias  acc[i][j] += sum_d Q[q,d]*embK[r(q,k),d] ----
    const int rbase = k0g - q0 + 873;          // r for (ii=127, jj=0)
    const int ewoff = (tx - ty) * 8 + 120;     // e-window byte base for this thread

    for (int c0 = 0; c0 < DK; c0 += 32) {
        // reload Q chunk (transposed) into As
        const float* Ap = Qb + (q0 + lr) * DK + c0 + lc;
        float4 av[4];
#pragma unroll
        for (int i = 0; i < 4; i++) av[i] = *(const float4*)(Ap + i*4);

        // embK window: rloc = tid (0..255; 255 is harmless padding), clamp r
        int rr = rbase + tid;
        int rc = rr < 0 ? 0 : (rr > 2000 ? 2000 : rr);
        const float* ep = embK + rc * DK + c0;
        float4 ev[8];
#pragma unroll
        for (int t = 0; t < 8; t++) ev[t] = *(const float4*)(ep + t*4);

        __syncthreads();
#pragma unroll
        for (int i = 0; i < 4; i++) {
            As[(lc+i*4+0)*128 + lr] = av[i].x; As[(lc+i*4+1)*128 + lr] = av[i].y;
            As[(lc+i*4+2)*128 + lr] = av[i].z; As[(lc+i*4+3)*128 + lr] = av[i].w;
        }
#pragma unroll
        for (int t = 0; t < 8; t++) {
            Es[(t*4+0)*ESTR + tid] = ev[t].x;
            Es[(t*4+1)*ESTR + tid] = ev[t].y;
            Es[(t*4+2)*ESTR + tid] = ev[t].z;
            Es[(t*4+3)*ESTR + tid] = ev[t].w;
        }
        __syncthreads();

#pragma unroll 8
        for (int d = 0; d < 32; d++) {
            float a[8];
            *(float4*)&a[0] = *(const float4*)&As[d*128 + ty*8];
            *(float4*)&a[4] = *(const float4*)&As[d*128 + ty*8+4];
            float e16[16];
            const float* ebase = &Es[d*ESTR + ewoff];
            *(float4*)&e16[0]  = *(const float4*)&ebase[0];
            *(float4*)&e16[4]  = *(const float4*)&ebase[4];
            *(float4*)&e16[8]  = *(const float4*)&ebase[8];
            *(float4*)&e16[12] = *(const float4*)&ebase[12];
#pragma unroll
            for (int i = 0; i < 8; i++)
#pragma unroll
                for (int j = 0; j < 8; j++)
                    acc[i][j] = fmaf(a[i], e16[j - i + 7], acc[i][j]);
        }
    }

    // ---- Epilogue ----
#pragma unroll
    for (int i = 0; i < 8; i++) {
        int q = q0 + ty*8 + i;
        float* lrow = g_logits + (size_t)bh * SS * SS + (size_t)q * SS;
#pragma unroll
        for (int j = 0; j < 8; j++)
            lrow[k0g + tx*8 + j] = acc[i][j];
    }
}

// ---------------------------------------------------------------------------
// Row softmax over g_logits -> wdst (weights output buffer or g_logits in place)
// ---------------------------------------------------------------------------
__global__ __launch_bounds__(256)
void softmax_kernel(float* __restrict__ wdst)
{
    __shared__ float red[8];
    const int row = blockIdx.x;
    const float* rp = g_logits + (size_t)row * SS;
    const int tid = threadIdx.x;

    float4 v = *(const float4*)&rp[tid * 4];
    float m = fmaxf(fmaxf(v.x, v.y), fmaxf(v.z, v.w));
#pragma unroll
    for (int o = 16; o; o >>= 1) m = fmaxf(m, __shfl_xor_sync(0xffffffffu, m, o));
    if ((tid & 31) == 0) red[tid >> 5] = m;
    __syncthreads();
    float bm = fmaxf(fmaxf(fmaxf(red[0], red[1]), fmaxf(red[2], red[3])),
                     fmaxf(fmaxf(red[4], red[5]), fmaxf(red[6], red[7])));

    float e0 = __expf(v.x - bm), e1 = __expf(v.y - bm);
    float e2 = __expf(v.z - bm), e3 = __expf(v.w - bm);
    float s = (e0 + e1) + (e2 + e3);
#pragma unroll
    for (int o = 16; o; o >>= 1) s += __shfl_xor_sync(0xffffffffu, s, o);
    __syncthreads();
    if ((tid & 31) == 0) red[tid >> 5] = s;
    __syncthreads();
    float bs = ((red[0] + red[1]) + (red[2] + red[3])) + ((red[4] + red[5]) + (red[6] + red[7]));
    float inv = 1.0f / bs;

    float4 o4 = make_float4(e0 * inv, e1 * inv, e2 * inv, e3 * inv);
    *(float4*)&wdst[(size_t)row * SS + tid * 4] = o4;
}

// ---------------------------------------------------------------------------
// AV kernel: x[bh,q,d] = sum_k w[q,k]*v[k,d] + sum_j wsh[q,j]*embV[j,d]
// wsh[q,j] aggregates w over the clipped relative index j = clamp(k-q+1000).
// Reads weights from wsrc (weights output buffer or g_logits).
// ---------------------------------------------------------------------------
__global__ __launch_bounds__(128, 4)
void attn_av(const float* __restrict__ embV, const float* __restrict__ wsrc)
{
    __shared__ float WsT[32][128];  // [k-or-j local][q local]
    __shared__ float Vs[32][68];    // [k-or-j local][d], padded stride

    const int bh = blockIdx.y;
    const int q0 = blockIdx.x * 128;
    const int tid = threadIdx.x;
    const int tx = tid & 7;         // d-group
    const int ty = tid >> 3;        // q-group (0..15)

    const float* wbase = wsrc + (size_t)bh * SS * SS;
    const float* vbase = g_v + bh * SS * DK;
    const int q = q0 + tid;                  // this thread's loader row
    const float* wr = wbase + (size_t)q * SS;

    float acc[8][8];
#pragma unroll
    for (int i = 0; i < 8; i++)
#pragma unroll
        for (int j = 0; j < 8; j++) acc[i][j] = 0.f;

    // ---- Phase 1: standard W @ V ----
    for (int k0 = 0; k0 < SS; k0 += 32) {
        __syncthreads();
#pragma unroll
        for (int i = 0; i < 8; i++) {
            float4 w4 = *(const float4*)&wr[k0 + i*4];
            WsT[i*4+0][tid] = w4.x; WsT[i*4+1][tid] = w4.y;
            WsT[i*4+2][tid] = w4.z; WsT[i*4+3][tid] = w4.w;
        }
        {
            int vrow = tid >> 2, cb = (tid & 3) * 16;
            const float* vp = vbase + (k0 + vrow) * DK + cb;
#pragma unroll
            for (int i = 0; i < 4; i++)
                *(float4*)&Vs[vrow][cb + i*4] = *(const float4*)&vp[i*4];
        }
        __syncthreads();
#pragma unroll 16
        for (int kk = 0; kk < 32; kk++) {
            float a[8], b[8];
            *(float4*)&a[0] = *(const float4*)&WsT[kk][ty*8];
            *(float4*)&a[4] = *(const float4*)&WsT[kk][ty*8+4];
            *(float4*)&b[0] = *(const float4*)&Vs[kk][tx*8];
            *(float4*)&b[4] = *(const float4*)&Vs[kk][tx*8+4];
#pragma unroll
            for (int i = 0; i < 8; i++)
#pragma unroll
                for (int j = 0; j < 8; j++)
                    acc[i][j] = fmaf(a[i], b[j], acc[i][j]);
        }
    }

    // ---- Phase 2: skewed W @ embV window ----
    const int jlo = max(0, 873 - q0);           // 1000 - (q0+127)
    const int jhi = min(2000, 2023 - q0);       // 1000 + (1023 - q0)
    for (int j0 = jlo; j0 <= jhi; j0 += 32) {
        __syncthreads();
        // Build skewed weights: wsh[q, j] (edge buckets at j=0 / j=2000 absorb clip)
        for (int jj = 0; jj < 32; jj++) {
            int j = j0 + jj;
            float val = 0.f;
            if (j > 0 && j < 2000) {
                int k = j + q - 1000;
                if ((unsigned)k < 1024u) val = wr[k];
            } else if (j == 0) {
                int kmax = q - 1000;             // only q >= 1000
                for (int k = 0; k <= kmax; k++) val += wr[k];
            } else if (j == 2000) {
                for (int k = q + 1000; k < 1024; k++) val += wr[k];  // only q <= 23
            }
            WsT[jj][tid] = val;
        }
        {
            int vrow = tid >> 2, cb = (tid & 3) * 16;
            int j = j0 + vrow;
            if (j < 2048) {
                const float* ep = embV + j * DK + cb;
#pragma unroll
                for (int i = 0; i < 4; i++)
                    *(float4*)&Vs[vrow][cb + i*4] = *(const float4*)&ep[i*4];
            } else {
#pragma unroll
                for (int i = 0; i < 4; i++)
                    *(float4*)&Vs[vrow][cb + i*4] = make_float4(0.f, 0.f, 0.f, 0.f);
            }
        }
        __syncthreads();
#pragma unroll 16
        for (int kk = 0; kk < 32; kk++) {
            float a[8], b[8];
            *(float4*)&a[0] = *(const float4*)&WsT[kk][ty*8];
            *(float4*)&a[4] = *(const float4*)&WsT[kk][ty*8+4];
            *(float4*)&b[0] = *(const float4*)&Vs[kk][tx*8];
            *(float4*)&b[4] = *(const float4*)&Vs[kk][tx*8+4];
#pragma unroll
            for (int i = 0; i < 8; i++)
#pragma unroll
                for (int j = 0; j < 8; j++)
                    acc[i][j] = fmaf(a[i], b[j], acc[i][j]);
        }
    }

    // epilogue: g_x[b, s=q, h*64+d]
    const int b = bh >> 4, h = bh & 15;
#pragma unroll
    for (int i = 0; i < 8; i++) {
        int qq = q0 + ty*8 + i;
#pragma unroll
        for (int j = 0; j < 8; j++)
            g_x[(b*SS + qq)*DM + h*DK + tx*8 + j] = acc[i][j];
    }
}

// ---------------------------------------------------------------------------
// Launch
// ---------------------------------------------------------------------------
extern "C" void kernel_launch(void* const* d_in, const int* in_sizes, int n_in,
                              void* d_out, int out_size)
{
    const float* query = (const float*)d_in[0];
    const float* key_  = (const float*)d_in[1];
    const float* value = (const float*)d_in[2];
    const float* Wq = (const float*)d_in[3];
    const float* bq = (const float*)d_in[4];
    const float* Wk = (const float*)d_in[5];
    const float* bk = (const float*)d_in[6];
    const float* Wv = (const float*)d_in[7];
    const float* bv = (const float*)d_in[8];
    const float* Wo = (const float*)d_in[9];
    const float* bo = (const float*)d_in[10];
    const float* embK = (const float*)d_in[11];
    const float* embV = (const float*)d_in[12];

    float* outp = (float*)d_out;
    const long OUT_N = (long)BI * SS * DM;        // 4,194,304  (out)
    const long W_N   = (long)BI * HH * SS * SS;   // 67,108,864 (weights)

    float* out_main = nullptr;
    float* out_w = nullptr;
    if ((long)out_size >= OUT_N + W_N) { out_main = outp; out_w = outp + OUT_N; }
    else if ((long)out_size >= W_N)    { out_w = outp; }
    else                               { out_main = outp; }

    cudaFuncSetAttribute(logits_fused, cudaFuncAttributeMaxDynamicSharedMemorySize,
                         LOGITS_SMEM);

    dim3 gp(DM / 128, (BI * SS) / 128);                       // (8, 32)
    gemm_proj<<<gp, 256>>>(query, Wq, bq, nullptr, 1);
    gemm_proj<<<gp, 256>>>(key_,  Wk, bk, nullptr, 2);
    gemm_proj<<<gp, 256>>>(value, Wv, bv, nullptr, 3);

    logits_fused<<<dim3(SS / 128, SS / 128, BI * HH), 256, LOGITS_SMEM>>>(embK); // (8,8,64)

    // softmax writes normalized weights once: to weights output if present,
    // else in place over g_logits; attn_av reads from the same place.
    float* wdst;
    cudaGetSymbolAddress((void**)&wdst, g_logits);
    if (out_w) wdst = out_w;

    softmax_kernel<<<BI * HH * SS, 256>>>(wdst);                         // 65536 rows

    attn_av<<<dim3(SS / 128, BI * HH), 128>>>(embV, wdst);               // (8, 64)

    if (out_main)
        gemm_proj<<<gp, 256>>>(nullptr, Wo, bo, out_main, 0);
}